// round 17
// baseline (speedup 1.0000x reference)
#include <cuda_runtime.h>

#define B_   256
#define IN_  256
#define OUT_ 512
#define EPS_ 1e-7f

__device__ float g_relx[IN_ * OUT_];   // rel_x[i][o]
__device__ int   g_iw[OUT_];           // argmax_i w[i,o]
__device__ float g_wv[OUT_];           // w[iw,o]
__device__ int   g_cnt[16];            // relx completion per o-tile-32 (reset in-kernel)
__device__ int   g_done[16];           // consumer count per o-tile-32
__device__ int   g_wcnt;               // w-argmax completion
__device__ int   g_wdone;              // w consumers

// ---------------------------------------------------------------------------
// Fused persistent kernel. Grid 512 x 256 threads (all blocks resident:
// <=4 blocks/SM x 41KB smem, no deadlock possible).
// Phase 1: bid<256 -> relx tile (R10 body, 32i x 16o); flags g_cnt[oy].
//          bid 256..271 -> w-argmax (32 o each); flags g_wcnt.
// Phase 2 (all 512): argmax tile 8b x 32o (R16 body), Xs prestaged before
// the spin, per-oy spin, direct outputs. Flags reset by last consumers.
// ---------------------------------------------------------------------------
__global__ void __launch_bounds__(256)
k_fused(const float* __restrict__ x, const float* __restrict__ w,
        const float* __restrict__ t,
        float* __restrict__ outx, float* __restrict__ outw) {
    __shared__ float sm[10272];        // 41088 B union
    const int bid = blockIdx.x;
    const int lid = threadIdx.x;

    // ======================= Phase 1 =======================
    if (bid < 256) {
        // ---- relx role: i0=(bid&7)*32, o0=(bid>>3)*16 (R10 body) ----
        float (*Rs)[32] = (float(*)[32])sm;           // 128x32
        float (*Ts)[16] = (float(*)[16])(sm + 4096);  // 128x16
        float (*ps)[32] = (float(*)[32])(sm + 6144);  // 8x32
        float *cs       = sm + 6400;                  // 32

        const int i0 = (bid & 7) * 32;
        const int o0 = (bid >> 3) * 16;
        const int to = lid & 15;
        const int tp = lid >> 4;

        {
            const int il = lid & 31, seg = lid >> 5;
            float s = 0.f;
            #pragma unroll
            for (int j = 0; j < 32; j++) s += x[(seg * 32 + j) * IN_ + i0 + il];
            ps[seg][il] = s;
        }

        float acc0 = 0.f, acc1 = 0.f;
        for (int bb = 0; bb < B_; bb += 128) {
            #pragma unroll
            for (int k = 0; k < 4; k++) {
                int e = lid + k * 256, row = e >> 3, c4 = (e & 7) * 4;
                float4 xv = *(const float4*)&x[(bb + row) * IN_ + i0 + c4];
                float4 rv;
                rv.x = 1.f / (xv.x + EPS_);
                rv.y = 1.f / (xv.y + EPS_);
                rv.z = 1.f / (xv.z + EPS_);
                rv.w = 1.f / (xv.w + EPS_);
                *(float4*)&Rs[row][c4] = rv;
            }
            #pragma unroll
            for (int k = 0; k < 2; k++) {
                int e = lid + k * 256, row = e >> 2, c4 = (e & 3) * 4;
                *(float4*)&Ts[row][c4] = *(const float4*)&t[(bb + row) * OUT_ + o0 + c4];
            }
            __syncthreads();

            if (bb == 0 && lid < 32) {
                float s = ps[0][lid];
                #pragma unroll
                for (int c = 1; c < 8; c++) s += ps[c][lid];
                cs[lid] = s;
            }

            #pragma unroll 8
            for (int b = 0; b < 128; b++) {
                float2 r  = *(const float2*)&Rs[b][2 * tp];
                float  tv = Ts[b][to];
                acc0 += fminf(tv * r.x, 1.f);
                acc1 += fminf(tv * r.y, 1.f);
            }
            __syncthreads();
        }
        const int i_0 = i0 + 2 * tp, i_1 = i_0 + 1, o = o0 + to;
        g_relx[i_0 * OUT_ + o] = acc0 / cs[2 * tp];
        g_relx[i_1 * OUT_ + o] = acc1 / cs[2 * tp + 1];
        __threadfence();
        __syncthreads();
        if (lid == 0) atomicAdd(&g_cnt[o0 >> 5], 1);
    } else if (bid < 272) {
        // ---- w-argmax role: 32 o's per block ----
        float *sv = sm;                 // 8x32 flat
        int   *si = (int*)(sm + 256);
        const int wb = bid - 256;
        const int ol = lid & 31, ic = lid >> 5;
        const int o  = wb * 32 + ol;
        float best = -1.f; int bi = 0;
        #pragma unroll
        for (int j = 0; j < 32; j++) {
            int i = ic * 32 + j;
            float v = w[i * OUT_ + o];
            if (v > best) { best = v; bi = i; }
        }
        sv[ic * 32 + ol] = best;
        si[ic * 32 + ol] = bi;
        __syncthreads();
        if (lid < 32) {
            float bv = sv[lid]; int ix = si[lid];
            #pragma unroll
            for (int c = 1; c < 8; c++)
                if (sv[c * 32 + lid] > bv) { bv = sv[c * 32 + lid]; ix = si[c * 32 + lid]; }
            g_wv[wb * 32 + lid] = bv;
            g_iw[wb * 32 + lid] = ix;
            __threadfence();
        }
        __syncthreads();
        if (lid == 0) atomicAdd(&g_wcnt, 1);
    }
    __syncthreads();   // smem role-reuse boundary

    // ======================= Phase 2: argmax (all 512 blocks) ===============
    float (*Xs)[260] = (float(*)[260])sm;           // 8x260
    float (*Rl)[32]  = (float(*)[32])(sm + 2080);   // 256x32

    const int b0   = (bid & 31) * 8;
    const int oy   = bid >> 5;
    const int o0a  = oy * 32;
    const int lane = lid & 31;
    const int bl   = lid >> 5;

    // stage Xs BEFORE the spin (overlaps other blocks' phase 1)
    #pragma unroll
    for (int k = 0; k < 2; k++) {
        int e = lid + k * 256, row = e >> 6, c4 = (e & 63) * 4;
        *(float4*)&Xs[row][c4] = *(const float4*)&x[(b0 + row) * IN_ + c4];
    }

    if (lid == 0) {
        while (atomicAdd(&g_cnt[oy], 0) < 16) __nanosleep(64);
        while (atomicAdd(&g_wcnt, 0) < 16)    __nanosleep(64);
    }
    __syncthreads();
    __threadfence();

    #pragma unroll
    for (int k = 0; k < 8; k++) {
        int e = lid + k * 256, row = e >> 3, c4 = (e & 7) * 4;
        *(float4*)&Rl[row][c4] = *(const float4*)&g_relx[row * OUT_ + o0a + c4];
    }
    __syncthreads();

    // fmax-only argmax + chunk tracking + in-smem rescan (R16 body)
    float best = -1.f; int bc = 0;
    #pragma unroll
    for (int c = 0; c < 8; c++) {
        float cm = -1.f;
        #pragma unroll
        for (int q = 0; q < 8; q++) {
            const int ib = c * 32 + q * 4;
            float4 xq = *(const float4*)&Xs[bl][ib];
            cm = fmaxf(cm, xq.x * Rl[ib + 0][lane]);
            cm = fmaxf(cm, xq.y * Rl[ib + 1][lane]);
            cm = fmaxf(cm, xq.z * Rl[ib + 2][lane]);
            cm = fmaxf(cm, xq.w * Rl[ib + 3][lane]);
        }
        if (cm > best) { best = cm; bc = c * 32; }
    }
    int id = bc;
    #pragma unroll 8
    for (int j = 31; j >= 0; j--)
        if (Xs[bl][bc + j] * Rl[bc + j][lane] == best) id = bc + j;

    const int b = b0 + bl, o = o0a + lane;
    outx[b * OUT_ + o] = x[b * IN_ + id] * w[id * OUT_ + o];
    outw[b * OUT_ + o] = x[b * IN_ + g_iw[o]] * g_wv[o];

    // in-kernel flag resets (replay-safe: next launch sees zeros)
    __syncthreads();
    if (lid == 0) {
        if (atomicAdd(&g_done[oy], 1) == 31) { g_cnt[oy] = 0; g_done[oy] = 0; }
        if (atomicAdd(&g_wdone, 1) == 511)   { g_wcnt   = 0; g_wdone   = 0; }
    }
}

// ---------------------------------------------------------------------------
extern "C" void kernel_launch(void* const* d_in, const int* in_sizes, int n_in,
                              void* d_out, int out_size) {
    const float* x = (const float*)d_in[0];
    const float* w = (const float*)d_in[1];
    const float* t = (const float*)d_in[2];
    float* outx = (float*)d_out;
    float* outw = (float*)d_out + B_ * OUT_;

    k_fused<<<512, 256>>>(x, w, t, outx, outw);
}